// round 7
// baseline (speedup 1.0000x reference)
#include <cuda_runtime.h>
#include <math.h>

// Problem constants (fixed shapes for this problem):
//   hidden_states [4,2048,1024] f32, gate_w [1024,8], w1/w3 [8,1024,4096],
//   w2 [8,4096,1024], out [4,2048,1024] f32, top_k = 2.
#define H_DIM 1024
#define E_NUM 8
#define I_DIM 4096
#define T_MAX 8192
#define CAP   T_MAX   // per-expert token capacity (worst case: all tokens)

// ---------------- scratch (device globals; no allocations allowed) ----------
__device__ int   g_top_idx[T_MAX * 2];
__device__ float g_top_w  [T_MAX * 2];
__device__ int   g_counts [E_NUM];
__device__ int   g_tok    [E_NUM * CAP];
__device__ float g_wlist  [E_NUM * CAP];
// SwiGLU intermediate h, bucketed per expert: [E][CAP][I]  (1 GiB, zero-init)
__device__ float g_h      [E_NUM * CAP * (size_t)I_DIM];

// ---------------- 1) router: logits -> softmax top-2 -> normalized weights --
// One warp per token. logits[e] = dot(x[t], gate_w[:,e]); top-2 of softmax
// normalized by their sum == 2-way softmax over the two top logits.
__global__ void router_kernel(const float* __restrict__ X,
                              const float* __restrict__ GW, int T) {
    int t    = (blockIdx.x * blockDim.x + threadIdx.x) >> 5;
    int lane = threadIdx.x & 31;
    if (t >= T) return;
    const float* xr = X + (size_t)t * H_DIM;
    float acc[E_NUM];
#pragma unroll
    for (int e = 0; e < E_NUM; ++e) acc[e] = 0.f;
    for (int k = lane; k < H_DIM; k += 32) {
        float  xv = __ldg(xr + k);
        float4 g0 = *(const float4*)(GW + (size_t)k * E_NUM);
        float4 g1 = *(const float4*)(GW + (size_t)k * E_NUM + 4);
        acc[0] += xv * g0.x; acc[1] += xv * g0.y;
        acc[2] += xv * g0.z; acc[3] += xv * g0.w;
        acc[4] += xv * g1.x; acc[5] += xv * g1.y;
        acc[6] += xv * g1.z; acc[7] += xv * g1.w;
    }
#pragma unroll
    for (int off = 16; off > 0; off >>= 1) {
#pragma unroll
        for (int e = 0; e < E_NUM; ++e)
            acc[e] += __shfl_xor_sync(0xffffffffu, acc[e], off);
    }
    if (lane == 0) {
        int i1 = 0;
#pragma unroll
        for (int e = 1; e < E_NUM; ++e) if (acc[e] > acc[i1]) i1 = e;
        int i2 = (i1 == 0) ? 1 : 0;
#pragma unroll
        for (int e = 0; e < E_NUM; ++e)
            if (e != i1 && acc[e] > acc[i2]) i2 = e;
        float d  = expf(acc[i2] - acc[i1]);    // <= 1
        float wa = 1.f / (1.f + d);
        g_top_idx[2*t]   = i1;  g_top_w[2*t]   = wa;
        g_top_idx[2*t+1] = i2;  g_top_w[2*t+1] = d / (1.f + d);
    }
}

// ---------------- 2) deterministic per-expert token compaction ---------------
// One block per expert; chunked ballot + block scan keeps token order stable.
__global__ void build_lists_kernel(int T) {
    const int e    = blockIdx.x;
    const int tid  = threadIdx.x;
    const int lane = tid & 31;
    const int wid  = tid >> 5;
    __shared__ int s_wsum[8];
    __shared__ int s_base;
    if (tid == 0) s_base = 0;
    __syncthreads();
    for (int start = 0; start < T; start += 256) {
        int   t    = start + tid;
        int   flag = 0;
        float w    = 0.f;
        if (t < T) {
            if      (g_top_idx[2*t]   == e) { flag = 1; w = g_top_w[2*t];   }
            else if (g_top_idx[2*t+1] == e) { flag = 1; w = g_top_w[2*t+1]; }
        }
        unsigned m = __ballot_sync(0xffffffffu, flag);
        if (lane == 0) s_wsum[wid] = __popc(m);
        __syncthreads();
        int off = s_base;
        for (int i = 0; i < wid; ++i) off += s_wsum[i];
        int pos = off + __popc(m & ((1u << lane) - 1u));
        if (flag) {
            g_tok  [e * CAP + pos] = t;
            g_wlist[e * CAP + pos] = w;
        }
        __syncthreads();
        if (tid == 0) {
            int tot = 0;
#pragma unroll
            for (int i = 0; i < 8; ++i) tot += s_wsum[i];
            s_base += tot;
        }
        __syncthreads();
    }
    if (tid == 0) g_counts[e] = s_base;
}

// ---------------- 3) GEMM1: h = silu(x@w1[e]) * (x@w3[e]) -------------------
// Dual-B GEMM: A tile (gathered x rows) shared between w1 and w3 products.
// BM=128, BN=64, BK=16, 256 threads, 8x4 per thread per matrix, double buffer.
#define BM1 128
#define BN1 64
#define BK1 16

__global__ void __launch_bounds__(256, 2)
moe_gemm1_kernel(const float* __restrict__ X,
                 const float* __restrict__ W1,
                 const float* __restrict__ W3) {
    const int e   = blockIdx.z;
    const int cnt = g_counts[e];
    const int m0  = blockIdx.y * BM1;
    if (m0 >= cnt) return;
    const int n0  = blockIdx.x * BN1;
    const int tid = threadIdx.x;

    __shared__ float As [2][BK1][BM1];
    __shared__ float B1s[2][BK1][BN1];
    __shared__ float B3s[2][BK1][BN1];
    __shared__ int   s_tok[BM1];

    if (tid < BM1) {
        int r = m0 + tid;
        s_tok[tid] = g_tok[e * CAP + (r < cnt ? r : 0)];  // cnt>0 guaranteed
    }
    __syncthreads();

    const float* B1p = W1 + (size_t)e * H_DIM * I_DIM + n0;
    const float* B3p = W3 + (size_t)e * H_DIM * I_DIM + n0;

    // A loads: thread covers row ar, float4 columns akq and akq+2 (BK1=16)
    const int    ar   = tid & 127;
    const int    akq  = tid >> 7;     // 0/1
    const float* Arow = X + (size_t)s_tok[ar] * H_DIM;

    // B loads: one float4 per matrix per thread
    const int bk = tid >> 4;          // 0..15
    const int bn = (tid & 15) * 4;    // 0..60

    const int ty = tid >> 4;          // 0..15 -> 8 rows each
    const int tx = tid & 15;          // 0..15 -> 4 cols each

    float acc1[8][4], acc3[8][4];
#pragma unroll
    for (int i = 0; i < 8; ++i)
#pragma unroll
        for (int j = 0; j < 4; ++j) { acc1[i][j] = 0.f; acc3[i][j] = 0.f; }

    float4 av0, av1, bv1, bv3;
    av0 = *(const float4*)(Arow + akq * 4);
    av1 = *(const float4*)(Arow + (akq + 2) * 4);
    bv1 = *(const float4*)(B1p + (size_t)bk * I_DIM + bn);
    bv3 = *(const float4*)(B3p + (size_t)bk * I_DIM + bn);
    As[0][akq*4+0][ar] = av0.x; As[0][akq*4+1][ar] = av0.y;
    As[0][akq*4+2][ar] = av0.z; As[0][akq*4+3][ar] = av0.w;
    As[0][(akq+2)*4+0][ar] = av1.x; As[0][(akq+2)*4+1][ar] = av1.y;
    As[0][(akq+2)*4+2][ar] = av1.z; As[0][(akq+2)*4+3][ar] = av1.w;
    *(float4*)&B1s[0][bk][bn] = bv1;
    *(float4*)&B3s[0][bk][bn] = bv3;
    __syncthreads();

    const int KT = H_DIM / BK1;   // 64
    for (int kt = 0; kt < KT; ++kt) {
        const int buf = kt & 1;
        if (kt + 1 < KT) {
            const int k1 = (kt + 1) * BK1;
            av0 = *(const float4*)(Arow + k1 + akq * 4);
            av1 = *(const float4*)(Arow + k1 + (akq + 2) * 4);
            bv1 = *(const float4*)(B1p + (size_t)(k1 + bk) * I_DIM + bn);
            bv3 = *(const float4*)(B3p + (size_t)(k1 + bk) * I_DIM + bn);
        }
#pragma unroll
        for (int kk = 0; kk < BK1; ++kk) {
            float4 a03 = *(const float4*)&As [buf][kk][ty * 8];
            float4 a47 = *(const float4*)&As [buf][kk][ty * 8 + 4];
            float4 b1  = *(const float4*)&B1s[buf][kk][tx * 4];
            float4 b3  = *(const float4*)&B3s[buf][kk][tx * 4];
            float a[8]  = {a03.x,a03.y,a03.z,a03.w,a47.x,a47.y,a47.z,a47.w};
            float c1[4] = {b1.x,b1.y,b1.z,b1.w};
            float c3[4] = {b3.x,b3.y,b3.z,b3.w};
#pragma unroll
            for (int i = 0; i < 8; ++i)
#pragma unroll
                for (int j = 0; j < 4; ++j) {
                    acc1[i][j] = fmaf(a[i], c1[j], acc1[i][j]);
                    acc3[i][j] = fmaf(a[i], c3[j], acc3[i][j]);
                }
        }
        if (kt + 1 < KT) {
            const int nb = buf ^ 1;
            As[nb][akq*4+0][ar] = av0.x; As[nb][akq*4+1][ar] = av0.y;
            As[nb][akq*4+2][ar] = av0.z; As[nb][akq*4+3][ar] = av0.w;
            As[nb][(akq+2)*4+0][ar] = av1.x; As[nb][(akq+2)*4+1][ar] = av1.y;
            As[nb][(akq+2)*4+2][ar] = av1.z; As[nb][(akq+2)*4+3][ar] = av1.w;
            *(float4*)&B1s[nb][bk][bn] = bv1;
            *(float4*)&B3s[nb][bk][bn] = bv3;
        }
        __syncthreads();
    }

    // SwiGLU epilogue -> g_h
#pragma unroll
    for (int i = 0; i < 8; ++i) {
        const int r = ty * 8 + i;
        if (m0 + r < cnt) {
            float* hp = g_h + ((size_t)e * CAP + m0 + r) * I_DIM + n0 + tx * 4;
            float4 o;
            float a0 = acc1[i][0], a1 = acc1[i][1];
            float a2 = acc1[i][2], a3 = acc1[i][3];
            o.x = (a0 / (1.f + expf(-a0))) * acc3[i][0];
            o.y = (a1 / (1.f + expf(-a1))) * acc3[i][1];
            o.z = (a2 / (1.f + expf(-a2))) * acc3[i][2];
            o.w = (a3 / (1.f + expf(-a3))) * acc3[i][3];
            *(float4*)hp = o;
        }
    }
}

// ---------------- 4) GEMM2: out[tok] += w * (h @ w2[e]) ----------------------
// BM=128, BN=128, BK=8, 256 threads, 8x8 per thread, double buffer.
// Scatter via atomicAdd: exactly two commutative adds per out element.
#define BM2 128
#define BN2 128
#define BK2 8

__global__ void __launch_bounds__(256, 2)
moe_gemm2_kernel(const float* __restrict__ W2, float* __restrict__ Out) {
    const int e   = blockIdx.z;
    const int cnt = g_counts[e];
    const int m0  = blockIdx.y * BM2;
    if (m0 >= cnt) return;
    const int n0  = blockIdx.x * BN2;
    const int tid = threadIdx.x;

    __shared__ float As[2][BK2][BM2];
    __shared__ float Bs[2][BK2][BN2];
    __shared__ int   s_tok[BM2];
    __shared__ float s_w  [BM2];

    if (tid < BM2) {
        int  r = m0 + tid;
        bool v = r < cnt;
        s_tok[tid] = v ? g_tok  [e * CAP + r] : 0;
        s_w  [tid] = v ? g_wlist[e * CAP + r] : 0.f;
    }

    const float* Ap = g_h + ((size_t)e * CAP + m0) * I_DIM;
    const float* Bp = W2 + (size_t)e * I_DIM * H_DIM + n0;

    const int ar  = tid & 127;
    const int akq = tid >> 7;       // 0/1 (row has 2 float4 for BK2=8)
    const int bk  = tid >> 5;       // 0..7
    const int bn  = (tid & 31) * 4; // 0..124

    const int ty = tid >> 4;
    const int tx = tid & 15;

    float acc[8][8];
#pragma unroll
    for (int i = 0; i < 8; ++i)
#pragma unroll
        for (int j = 0; j < 8; ++j) acc[i][j] = 0.f;

    float4 av, bv;
    av = *(const float4*)(Ap + (size_t)ar * I_DIM + akq * 4);
    bv = *(const float4*)(Bp + (size_t)bk * H_DIM + bn);
    As[0][akq*4+0][ar] = av.x; As[0][akq*4+1][ar] = av.y;
    As[0][akq*4+2][ar] = av.z; As[0][akq*4+3][ar] = av.w;
    *(float4*)&Bs[0][bk][bn] = bv;
    __syncthreads();

    const int KT = I_DIM / BK2;   // 512
    for (int kt = 0; kt < KT; ++kt) {
        const int buf = kt & 1;
        if (kt + 1 < KT) {
            const int k1 = (kt + 1) * BK2;
            av = *(const float4*)(Ap + (size_t)ar * I_DIM + k1 + akq * 4);
            bv = *(const float4*)(Bp + (size_t)(k1 + bk) * H_DIM + bn);
        }
#pragma unroll
        for (int kk = 0; kk < BK2; ++kk) {
            float4 a03 = *(const float4*)&As[buf][kk][ty * 8];
            float4 a47 = *(const float4*)&As[buf][kk][ty * 8 + 4];
            float4 b03 = *(const float4*)&Bs[buf][kk][tx * 8];
            float4 b47 = *(const float4*)&Bs[buf][kk][tx * 8 + 4];
            float a[8] = {a03.x,a03.y,a03.z,a03.w,a47.x,a47.y,a47.z,a47.w};
            float b[8] = {b03.x,b03.y,b03.z,b03.w,b47.x,b47.y,b47.z,b47.w};
#pragma unroll
            for (int i = 0; i < 8; ++i)
#pragma unroll
                for (int j = 0; j < 8; ++j)
                    acc[i][j] = fmaf(a[i], b[j], acc[i][j]);
        }
        if (kt + 1 < KT) {
            const int nb = buf ^ 1;
            As[nb][akq*4+0][ar] = av.x; As[nb][akq*4+1][ar] = av.y;
            As[nb][akq*4+2][ar] = av.z; As[nb][akq*4+3][ar] = av.w;
            *(float4*)&Bs[nb][bk][bn] = bv;
        }
        __syncthreads();
    }

#pragma unroll
    for (int i = 0; i < 8; ++i) {
        const int r = ty * 8 + i;
        if (m0 + r < cnt) {
            const float w  = s_w[r];
            float*      op = Out + (size_t)s_tok[r] * H_DIM + n0 + tx * 8;
#pragma unroll
            for (int j = 0; j < 8; ++j)
                atomicAdd(op + j, acc[i][j] * w);
        }
    }
}

// ---------------- launch ----------------------------------------------------
extern "C" void kernel_launch(void* const* d_in, const int* in_sizes, int n_in,
                              void* d_out, int out_size) {
    const float* x  = (const float*)d_in[0];
    const float* gw = (const float*)d_in[1];
    const float* w1 = (const float*)d_in[2];
    const float* w3 = (const float*)d_in[3];
    const float* w2 = (const float*)d_in[4];
    float* out = (float*)d_out;
    const int T = in_sizes[0] / H_DIM;

    cudaMemsetAsync(d_out, 0, (size_t)out_size * sizeof(float), 0);
    router_kernel<<<(T + 7) / 8, 256>>>(x, gw, T);
    build_lists_kernel<<<E_NUM, 256>>>(T);
    dim3 g1(I_DIM / BN1, (T + BM1 - 1) / BM1, E_NUM);
    moe_gemm1_kernel<<<g1, 256>>>(x, w1, w3);
    dim3 g2(H_DIM / BN2, (T + BM2 - 1) / BM2, E_NUM);
    moe_gemm2_kernel<<<g2, 256>>>(w2, out);
}

// round 8
// speedup vs baseline: 1.0003x; 1.0003x over previous
#include <cuda_runtime.h>
#include <math.h>

// Problem constants (fixed shapes for this problem):
//   hidden_states [4,2048,1024] f32, gate_w [1024,8], w1/w3 [8,1024,4096],
//   w2 [8,4096,1024], out [4,2048,1024] f32, top_k = 2.
#define H_DIM 1024
#define E_NUM 8
#define I_DIM 4096
#define T_MAX 8192
#define CAP   T_MAX   // per-expert token capacity (worst case: all tokens)

// ---------------- scratch (device globals; no allocations allowed) ----------
__device__ int   g_top_idx[T_MAX * 2];
__device__ float g_top_w  [T_MAX * 2];
__device__ int   g_counts [E_NUM];
__device__ int   g_tok    [E_NUM * CAP];
__device__ float g_wlist  [E_NUM * CAP];
// SwiGLU intermediate h, bucketed per expert: [E][CAP][I]  (1 GiB, zero-init)
__device__ float g_h      [E_NUM * CAP * (size_t)I_DIM];

// ---------------- 1) router: logits -> softmax top-2 -> normalized weights --
// One warp per token. logits[e] = dot(x[t], gate_w[:,e]); top-2 of softmax
// normalized by their sum == 2-way softmax over the two top logits.
__global__ void router_kernel(const float* __restrict__ X,
                              const float* __restrict__ GW, int T) {
    int t    = (blockIdx.x * blockDim.x + threadIdx.x) >> 5;
    int lane = threadIdx.x & 31;
    if (t >= T) return;
    const float* xr = X + (size_t)t * H_DIM;
    float acc[E_NUM];
#pragma unroll
    for (int e = 0; e < E_NUM; ++e) acc[e] = 0.f;
    for (int k = lane; k < H_DIM; k += 32) {
        float  xv = __ldg(xr + k);
        float4 g0 = *(const float4*)(GW + (size_t)k * E_NUM);
        float4 g1 = *(const float4*)(GW + (size_t)k * E_NUM + 4);
        acc[0] += xv * g0.x; acc[1] += xv * g0.y;
        acc[2] += xv * g0.z; acc[3] += xv * g0.w;
        acc[4] += xv * g1.x; acc[5] += xv * g1.y;
        acc[6] += xv * g1.z; acc[7] += xv * g1.w;
    }
#pragma unroll
    for (int off = 16; off > 0; off >>= 1) {
#pragma unroll
        for (int e = 0; e < E_NUM; ++e)
            acc[e] += __shfl_xor_sync(0xffffffffu, acc[e], off);
    }
    if (lane == 0) {
        int i1 = 0;
#pragma unroll
        for (int e = 1; e < E_NUM; ++e) if (acc[e] > acc[i1]) i1 = e;
        int i2 = (i1 == 0) ? 1 : 0;
#pragma unroll
        for (int e = 0; e < E_NUM; ++e)
            if (e != i1 && acc[e] > acc[i2]) i2 = e;
        float d  = expf(acc[i2] - acc[i1]);    // <= 1
        float wa = 1.f / (1.f + d);
        g_top_idx[2*t]   = i1;  g_top_w[2*t]   = wa;
        g_top_idx[2*t+1] = i2;  g_top_w[2*t+1] = d / (1.f + d);
    }
}

// ---------------- 2) deterministic per-expert token compaction ---------------
// One block per expert; chunked ballot + block scan keeps token order stable.
__global__ void build_lists_kernel(int T) {
    const int e    = blockIdx.x;
    const int tid  = threadIdx.x;
    const int lane = tid & 31;
    const int wid  = tid >> 5;
    __shared__ int s_wsum[8];
    __shared__ int s_base;
    if (tid == 0) s_base = 0;
    __syncthreads();
    for (int start = 0; start < T; start += 256) {
        int   t    = start + tid;
        int   flag = 0;
        float w    = 0.f;
        if (t < T) {
            if      (g_top_idx[2*t]   == e) { flag = 1; w = g_top_w[2*t];   }
            else if (g_top_idx[2*t+1] == e) { flag = 1; w = g_top_w[2*t+1]; }
        }
        unsigned m = __ballot_sync(0xffffffffu, flag);
        if (lane == 0) s_wsum[wid] = __popc(m);
        __syncthreads();
        int off = s_base;
        for (int i = 0; i < wid; ++i) off += s_wsum[i];
        int pos = off + __popc(m & ((1u << lane) - 1u));
        if (flag) {
            g_tok  [e * CAP + pos] = t;
            g_wlist[e * CAP + pos] = w;
        }
        __syncthreads();
        if (tid == 0) {
            int tot = 0;
#pragma unroll
            for (int i = 0; i < 8; ++i) tot += s_wsum[i];
            s_base += tot;
        }
        __syncthreads();
    }
    if (tid == 0) g_counts[e] = s_base;
}

// ---------------- 3) GEMM1: h = silu(x@w1[e]) * (x@w3[e]) -------------------
// Dual-B GEMM: A tile (gathered x rows) shared between w1 and w3 products.
// BM=128, BN=64, BK=16, 256 threads, 8x4 per thread per matrix, double buffer.
#define BM1 128
#define BN1 64
#define BK1 16

__global__ void __launch_bounds__(256, 2)
moe_gemm1_kernel(const float* __restrict__ X,
                 const float* __restrict__ W1,
                 const float* __restrict__ W3) {
    const int e   = blockIdx.z;
    const int cnt = g_counts[e];
    const int m0  = blockIdx.y * BM1;
    if (m0 >= cnt) return;
    const int n0  = blockIdx.x * BN1;
    const int tid = threadIdx.x;

    __shared__ float As [2][BK1][BM1];
    __shared__ float B1s[2][BK1][BN1];
    __shared__ float B3s[2][BK1][BN1];
    __shared__ int   s_tok[BM1];

    if (tid < BM1) {
        int r = m0 + tid;
        s_tok[tid] = g_tok[e * CAP + (r < cnt ? r : 0)];  // cnt>0 guaranteed
    }
    __syncthreads();

    const float* B1p = W1 + (size_t)e * H_DIM * I_DIM + n0;
    const float* B3p = W3 + (size_t)e * H_DIM * I_DIM + n0;

    // A loads: thread covers row ar, float4 columns akq and akq+2 (BK1=16)
    const int    ar   = tid & 127;
    const int    akq  = tid >> 7;     // 0/1
    const float* Arow = X + (size_t)s_tok[ar] * H_DIM;

    // B loads: one float4 per matrix per thread
    const int bk = tid >> 4;          // 0..15
    const int bn = (tid & 15) * 4;    // 0..60

    const int ty = tid >> 4;          // 0..15 -> 8 rows each
    const int tx = tid & 15;          // 0..15 -> 4 cols each

    float acc1[8][4], acc3[8][4];
#pragma unroll
    for (int i = 0; i < 8; ++i)
#pragma unroll
        for (int j = 0; j < 4; ++j) { acc1[i][j] = 0.f; acc3[i][j] = 0.f; }

    float4 av0, av1, bv1, bv3;
    av0 = *(const float4*)(Arow + akq * 4);
    av1 = *(const float4*)(Arow + (akq + 2) * 4);
    bv1 = *(const float4*)(B1p + (size_t)bk * I_DIM + bn);
    bv3 = *(const float4*)(B3p + (size_t)bk * I_DIM + bn);
    As[0][akq*4+0][ar] = av0.x; As[0][akq*4+1][ar] = av0.y;
    As[0][akq*4+2][ar] = av0.z; As[0][akq*4+3][ar] = av0.w;
    As[0][(akq+2)*4+0][ar] = av1.x; As[0][(akq+2)*4+1][ar] = av1.y;
    As[0][(akq+2)*4+2][ar] = av1.z; As[0][(akq+2)*4+3][ar] = av1.w;
    *(float4*)&B1s[0][bk][bn] = bv1;
    *(float4*)&B3s[0][bk][bn] = bv3;
    __syncthreads();

    const int KT = H_DIM / BK1;   // 64
    for (int kt = 0; kt < KT; ++kt) {
        const int buf = kt & 1;
        if (kt + 1 < KT) {
            const int k1 = (kt + 1) * BK1;
            av0 = *(const float4*)(Arow + k1 + akq * 4);
            av1 = *(const float4*)(Arow + k1 + (akq + 2) * 4);
            bv1 = *(const float4*)(B1p + (size_t)(k1 + bk) * I_DIM + bn);
            bv3 = *(const float4*)(B3p + (size_t)(k1 + bk) * I_DIM + bn);
        }
#pragma unroll
        for (int kk = 0; kk < BK1; ++kk) {
            float4 a03 = *(const float4*)&As [buf][kk][ty * 8];
            float4 a47 = *(const float4*)&As [buf][kk][ty * 8 + 4];
            float4 b1  = *(const float4*)&B1s[buf][kk][tx * 4];
            float4 b3  = *(const float4*)&B3s[buf][kk][tx * 4];
            float a[8]  = {a03.x,a03.y,a03.z,a03.w,a47.x,a47.y,a47.z,a47.w};
            float c1[4] = {b1.x,b1.y,b1.z,b1.w};
            float c3[4] = {b3.x,b3.y,b3.z,b3.w};
#pragma unroll
            for (int i = 0; i < 8; ++i)
#pragma unroll
                for (int j = 0; j < 4; ++j) {
                    acc1[i][j] = fmaf(a[i], c1[j], acc1[i][j]);
                    acc3[i][j] = fmaf(a[i], c3[j], acc3[i][j]);
                }
        }
        if (kt + 1 < KT) {
            const int nb = buf ^ 1;
            As[nb][akq*4+0][ar] = av0.x; As[nb][akq*4+1][ar] = av0.y;
            As[nb][akq*4+2][ar] = av0.z; As[nb][akq*4+3][ar] = av0.w;
            As[nb][(akq+2)*4+0][ar] = av1.x; As[nb][(akq+2)*4+1][ar] = av1.y;
            As[nb][(akq+2)*4+2][ar] = av1.z; As[nb][(akq+2)*4+3][ar] = av1.w;
            *(float4*)&B1s[nb][bk][bn] = bv1;
            *(float4*)&B3s[nb][bk][bn] = bv3;
        }
        __syncthreads();
    }

    // SwiGLU epilogue -> g_h
#pragma unroll
    for (int i = 0; i < 8; ++i) {
        const int r = ty * 8 + i;
        if (m0 + r < cnt) {
            float* hp = g_h + ((size_t)e * CAP + m0 + r) * I_DIM + n0 + tx * 4;
            float4 o;
            float a0 = acc1[i][0], a1 = acc1[i][1];
            float a2 = acc1[i][2], a3 = acc1[i][3];
            o.x = (a0 / (1.f + expf(-a0))) * acc3[i][0];
            o.y = (a1 / (1.f + expf(-a1))) * acc3[i][1];
            o.z = (a2 / (1.f + expf(-a2))) * acc3[i][2];
            o.w = (a3 / (1.f + expf(-a3))) * acc3[i][3];
            *(float4*)hp = o;
        }
    }
}

// ---------------- 4) GEMM2: out[tok] += w * (h @ w2[e]) ----------------------
// BM=128, BN=128, BK=8, 256 threads, 8x8 per thread, double buffer.
// Scatter via atomicAdd: exactly two commutative adds per out element.
#define BM2 128
#define BN2 128
#define BK2 8

__global__ void __launch_bounds__(256, 2)
moe_gemm2_kernel(const float* __restrict__ W2, float* __restrict__ Out) {
    const int e   = blockIdx.z;
    const int cnt = g_counts[e];
    const int m0  = blockIdx.y * BM2;
    if (m0 >= cnt) return;
    const int n0  = blockIdx.x * BN2;
    const int tid = threadIdx.x;

    __shared__ float As[2][BK2][BM2];
    __shared__ float Bs[2][BK2][BN2];
    __shared__ int   s_tok[BM2];
    __shared__ float s_w  [BM2];

    if (tid < BM2) {
        int  r = m0 + tid;
        bool v = r < cnt;
        s_tok[tid] = v ? g_tok  [e * CAP + r] : 0;
        s_w  [tid] = v ? g_wlist[e * CAP + r] : 0.f;
    }

    const float* Ap = g_h + ((size_t)e * CAP + m0) * I_DIM;
    const float* Bp = W2 + (size_t)e * I_DIM * H_DIM + n0;

    const int ar  = tid & 127;
    const int akq = tid >> 7;       // 0/1 (row has 2 float4 for BK2=8)
    const int bk  = tid >> 5;       // 0..7
    const int bn  = (tid & 31) * 4; // 0..124

    const int ty = tid >> 4;
    const int tx = tid & 15;

    float acc[8][8];
#pragma unroll
    for (int i = 0; i < 8; ++i)
#pragma unroll
        for (int j = 0; j < 8; ++j) acc[i][j] = 0.f;

    float4 av, bv;
    av = *(const float4*)(Ap + (size_t)ar * I_DIM + akq * 4);
    bv = *(const float4*)(Bp + (size_t)bk * H_DIM + bn);
    As[0][akq*4+0][ar] = av.x; As[0][akq*4+1][ar] = av.y;
    As[0][akq*4+2][ar] = av.z; As[0][akq*4+3][ar] = av.w;
    *(float4*)&Bs[0][bk][bn] = bv;
    __syncthreads();

    const int KT = I_DIM / BK2;   // 512
    for (int kt = 0; kt < KT; ++kt) {
        const int buf = kt & 1;
        if (kt + 1 < KT) {
            const int k1 = (kt + 1) * BK2;
            av = *(const float4*)(Ap + (size_t)ar * I_DIM + k1 + akq * 4);
            bv = *(const float4*)(Bp + (size_t)(k1 + bk) * H_DIM + bn);
        }
#pragma unroll
        for (int kk = 0; kk < BK2; ++kk) {
            float4 a03 = *(const float4*)&As[buf][kk][ty * 8];
            float4 a47 = *(const float4*)&As[buf][kk][ty * 8 + 4];
            float4 b03 = *(const float4*)&Bs[buf][kk][tx * 8];
            float4 b47 = *(const float4*)&Bs[buf][kk][tx * 8 + 4];
            float a[8] = {a03.x,a03.y,a03.z,a03.w,a47.x,a47.y,a47.z,a47.w};
            float b[8] = {b03.x,b03.y,b03.z,b03.w,b47.x,b47.y,b47.z,b47.w};
#pragma unroll
            for (int i = 0; i < 8; ++i)
#pragma unroll
                for (int j = 0; j < 8; ++j)
                    acc[i][j] = fmaf(a[i], b[j], acc[i][j]);
        }
        if (kt + 1 < KT) {
            const int nb = buf ^ 1;
            As[nb][akq*4+0][ar] = av.x; As[nb][akq*4+1][ar] = av.y;
            As[nb][akq*4+2][ar] = av.z; As[nb][akq*4+3][ar] = av.w;
            *(float4*)&Bs[nb][bk][bn] = bv;
        }
        __syncthreads();
    }

#pragma unroll
    for (int i = 0; i < 8; ++i) {
        const int r = ty * 8 + i;
        if (m0 + r < cnt) {
            const float w  = s_w[r];
            float*      op = Out + (size_t)s_tok[r] * H_DIM + n0 + tx * 8;
#pragma unroll
            for (int j = 0; j < 8; ++j)
                atomicAdd(op + j, acc[i][j] * w);
        }
    }
}

// ---------------- launch ----------------------------------------------------
extern "C" void kernel_launch(void* const* d_in, const int* in_sizes, int n_in,
                              void* d_out, int out_size) {
    const float* x  = (const float*)d_in[0];
    const float* gw = (const float*)d_in[1];
    const float* w1 = (const float*)d_in[2];
    const float* w3 = (const float*)d_in[3];
    const float* w2 = (const float*)d_in[4];
    float* out = (float*)d_out;
    const int T = in_sizes[0] / H_DIM;

    cudaMemsetAsync(d_out, 0, (size_t)out_size * sizeof(float), 0);
    router_kernel<<<(T + 7) / 8, 256>>>(x, gw, T);
    build_lists_kernel<<<E_NUM, 256>>>(T);
    dim3 g1(I_DIM / BN1, (T + BM1 - 1) / BM1, E_NUM);
    moe_gemm1_kernel<<<g1, 256>>>(x, w1, w3);
    dim3 g2(H_DIM / BN2, (T + BM2 - 1) / BM2, E_NUM);
    moe_gemm2_kernel<<<g2, 256>>>(w2, out);
}